// round 16
// baseline (speedup 1.0000x reference)
#include <cuda_runtime.h>
#include <cuda_bf16.h>
#include <cstdint>

#define PAD_VAL  -1000.0f
#define ROW      4096
#define NROWS    1024
#define SEGF     1024          // owned floats per segment
#define NSEG     4
#define NCHK     256           // owned 4-float chunks
#define HALO     16            // halo chunks (next 64 floats)
#define RPB      4             // rows per block
#define RAWF     (SEGF + 64)   // 1088 floats per row incl. halo
#define PLANE    (NCHK + HALO) // 272
#define THREADS  256

// out[i] = relu( max_{j=1..64} h[i+j]-j - h[i] ), right-pad -1000.
// Segment-local frame G[t'] = h[t'] - t':
//   out[t'] = relu( max G[t'+1..t'+64] - G[t'] )
// Data path: threads 0-3 each issue one cp.async.bulk (one row, 4352B incl.
// halo) into smem against ONE mbarrier (expect_tx = total, set by t0). All
// warps wait once, then compute from smem:
//   own chunk  : 1 LDS.128
//   mid        : 15 scalar LDS of the chunk-max plane
//   B-prefix   : 1 LDS.128 of chunk t+16 raw + 3 fmax
__global__ __launch_bounds__(THREADS, 7) void h2i_kernel(
    const float* __restrict__ hf, float* __restrict__ out)
{
    const int t   = threadIdx.x;
    const int rg  = blockIdx.x >> 2;
    const int seg = blockIdx.x & (NSEG - 1);
    const size_t base0 = ((size_t)rg * RPB) * ROW + (size_t)seg * SEGF;
    const bool last = (seg == NSEG - 1);

    __shared__ alignas(16) float raw[RPB][RAWF];
    __shared__ float sM[RPB][PLANE];
    __shared__ alignas(8) uint64_t mbar;

    uint32_t mbar_a;
    asm volatile("{ .reg .u64 x; cvta.to.shared.u64 x, %1; cvt.u32.u64 %0, x; }"
                 : "=r"(mbar_a) : "l"(&mbar));

    if (t == 0)
        asm volatile("mbarrier.init.shared.b64 [%0], 1;" :: "r"(mbar_a) : "memory");
    __syncthreads();

    const uint32_t row_bytes = last ? SEGF * 4u : RAWF * 4u;
    if (t == 0)
        asm volatile("mbarrier.arrive.expect_tx.shared.b64 _, [%0], %1;"
                     :: "r"(mbar_a), "r"(row_bytes * RPB) : "memory");
    if (t < RPB) {                               // parallel TMA issue: 1 row/thread
        const int j = t;
        uint32_t dst;
        asm volatile("{ .reg .u64 x; cvta.to.shared.u64 x, %1; cvt.u32.u64 %0, x; }"
                     : "=r"(dst) : "l"(&raw[j][0]));
        const float* src = hf + base0 + (size_t)j * ROW;
        asm volatile(
            "cp.async.bulk.shared::cta.global.mbarrier::complete_tx::bytes "
            "[%0], [%1], %2, [%3];"
            :: "r"(dst), "l"(src), "r"(row_bytes), "r"(mbar_a) : "memory");
    }

    // sentinel halo for the last segment (region excluded from the copy)
    if (last) {                                  // 256 floats, one per thread
        const int j = t >> 6, idx = t & 63;
        raw[j][SEGF + idx] = PAD_VAL;
    }

    // ---- wait for all 4 bulk copies (acquire orders the smem reads below) ----
    {
        uint32_t done;
        asm volatile(
            "{\n\t.reg .pred p;\n\t"
            "mbarrier.try_wait.parity.acquire.cta.shared::cta.b64 p, [%1], 0;\n\t"
            "selp.b32 %0, 1, 0, p;\n\t}"
            : "=r"(done) : "r"(mbar_a) : "memory");
        while (!done) {
            asm volatile(
                "{\n\t.reg .pred p;\n\t"
                "mbarrier.try_wait.parity.acquire.cta.shared::cta.b64 p, [%1], 0, 0x989680;\n\t"
                "selp.b32 %0, 1, 0, p;\n\t}"
                : "=r"(done) : "r"(mbar_a) : "memory");
        }
    }
    __syncthreads();                             // all lanes past wait + halo fill

    // ---- per-row: own chunk from smem, G-frame, chunk-max plane ----
    const float tb = (float)(4 * t);
    float g[RPB][4];
    #pragma unroll
    for (int j = 0; j < RPB; j++) {
        float4 a = ((const float4*)&raw[j][0])[t];
        g[j][0] = a.x - tb;
        g[j][1] = a.y - (tb + 1.0f);
        g[j][2] = a.z - (tb + 2.0f);
        g[j][3] = a.w - (tb + 3.0f);
        sM[j][t] = fmaxf(fmaxf(g[j][0], g[j][1]), fmaxf(g[j][2], g[j][3]));
    }
    if (t < 64) {                                // halo chunk maxes
        const int j2 = t >> 4, ht = t & 15;
        float4 a = ((const float4*)&raw[j2][0])[NCHK + ht];
        const float hb = (float)(SEGF + 4 * ht);
        sM[j2][NCHK + ht] =
            fmaxf(fmaxf(a.x - hb,          a.y - (hb + 1.0f)),
                  fmaxf(a.z - (hb + 2.0f), a.w - (hb + 3.0f)));
    }
    __syncthreads();

    // ---- combine + store ----
    #pragma unroll
    for (int j = 0; j < RPB; j++) {
        float mid = sM[j][t + 1];
        #pragma unroll
        for (int k = 2; k <= 15; k++)
            mid = fmaxf(mid, sM[j][t + k]);

        // B-prefix of chunk t+16 straight from raw
        float4 b = ((const float4*)&raw[j][0])[t + 16];
        const float bb = tb + 64.0f;
        const float B0 = b.x - bb;
        const float B1 = fmaxf(B0, b.y - (bb + 1.0f));
        const float B2 = fmaxf(B1, b.z - (bb + 2.0f));
        const float B3 = fmaxf(B2, b.w - (bb + 3.0f));

        const float suf2 = g[j][3];
        const float suf1 = fmaxf(g[j][2], suf2);
        const float suf0 = fmaxf(g[j][1], suf1);

        float w, r0, r1, r2, r3;
        w = fmaxf(fmaxf(suf0, mid), B0); r0 = fmaxf(w - g[j][0], 0.0f);
        w = fmaxf(fmaxf(suf1, mid), B1); r1 = fmaxf(w - g[j][1], 0.0f);
        w = fmaxf(fmaxf(suf2, mid), B2); r2 = fmaxf(w - g[j][2], 0.0f);
        w = fmaxf(mid, B3);              r3 = fmaxf(w - g[j][3], 0.0f);

        ((float4*)(out + base0 + (size_t)j * ROW))[t] = make_float4(r0, r1, r2, r3);
    }
}

extern "C" void kernel_launch(void* const* d_in, const int* in_sizes, int n_in,
                              void* d_out, int out_size)
{
    const float* hf  = (const float*)d_in[0];
    float*       out = (float*)d_out;
    (void)in_sizes; (void)n_in; (void)out_size;
    cudaFuncSetAttribute(h2i_kernel,
                         cudaFuncAttributePreferredSharedMemoryCarveout,
                         cudaSharedmemCarveoutMaxShared);
    // 256 row-groups x 4 segments = 1024 blocks; 7/SM -> single wave
    h2i_kernel<<<(NROWS / RPB) * NSEG, THREADS>>>(hf, out);
}

// round 17
// speedup vs baseline: 1.2583x; 1.2583x over previous
#include <cuda_runtime.h>
#include <cuda_bf16.h>
#include <cstdint>

#define PAD_VAL  -1000.0f
#define ROW      4096
#define NROWS    1024
#define SEGF     1024          // owned floats per segment
#define NSEG     4
#define NCHK     256           // owned 4-float chunks
#define HALO     16            // halo chunks (next 64 floats)
#define RPB      4             // rows per block
#define RAWF     (SEGF + 64)   // 1088 floats per row incl. halo
#define PLANE    (NCHK + HALO) // 272
#define THREADS  256

// out[i] = relu( max_{j=1..64} h[i+j]-j - h[i] ), right-pad -1000.
// Segment-local frame G[t'] = h[t'] - t':
//   out[t'] = relu( max G[t'+1..t'+64] - G[t'] )
// Data path: thread 0 issues 4 cp.async.bulk (one per row, 4352B incl. halo)
// into smem against ONE mbarrier (expect_tx = total). No register LDG
// front-batching — warps wait once on the mbarrier, then compute from smem:
//   own chunk  : 1 LDS.128
//   mid        : 15 scalar LDS of the chunk-max plane
//   B-prefix   : 1 LDS.128 of chunk t+16 raw + 3 fmax (no prefix planes)
__global__ __launch_bounds__(THREADS, 7) void h2i_kernel(
    const float* __restrict__ hf, float* __restrict__ out)
{
    const int t   = threadIdx.x;
    const int rg  = blockIdx.x >> 2;
    const int seg = blockIdx.x & (NSEG - 1);
    const size_t base0 = ((size_t)rg * RPB) * ROW + (size_t)seg * SEGF;
    const bool last = (seg == NSEG - 1);

    __shared__ alignas(16) float raw[RPB][RAWF];
    __shared__ float sM[RPB][PLANE];
    __shared__ alignas(8) uint64_t mbar;

    // smem addresses (shared-window) for PTX
    uint32_t mbar_a;
    asm volatile("{ .reg .u64 x; cvta.to.shared.u64 x, %1; cvt.u32.u64 %0, x; }"
                 : "=r"(mbar_a) : "l"(&mbar));

    if (t == 0)
        asm volatile("mbarrier.init.shared.b64 [%0], 1;" :: "r"(mbar_a) : "memory");
    __syncthreads();

    const uint32_t row_bytes = last ? SEGF * 4u : RAWF * 4u;
    if (t == 0) {
        asm volatile("mbarrier.arrive.expect_tx.shared.b64 _, [%0], %1;"
                     :: "r"(mbar_a), "r"(row_bytes * RPB) : "memory");
        #pragma unroll
        for (int j = 0; j < RPB; j++) {
            uint32_t dst;
            asm volatile("{ .reg .u64 x; cvta.to.shared.u64 x, %1; cvt.u32.u64 %0, x; }"
                         : "=r"(dst) : "l"(&raw[j][0]));
            const float* src = hf + base0 + (size_t)j * ROW;
            asm volatile(
                "cp.async.bulk.shared::cta.global.mbarrier::complete_tx::bytes "
                "[%0], [%1], %2, [%3];"
                :: "r"(dst), "l"(src), "r"(row_bytes), "r"(mbar_a) : "memory");
        }
    }

    // sentinel halo for the last segment (different smem region than the copy)
    if (last) {                                  // 256 floats, one per thread
        const int j = t >> 6, idx = t & 63;
        raw[j][SEGF + idx] = PAD_VAL;
    }

    // ---- wait for all 4 bulk copies (acquire orders the smem reads below) ----
    {
        uint32_t done;
        asm volatile(
            "{\n\t.reg .pred p;\n\t"
            "mbarrier.try_wait.parity.acquire.cta.shared::cta.b64 p, [%1], 0;\n\t"
            "selp.b32 %0, 1, 0, p;\n\t}"
            : "=r"(done) : "r"(mbar_a) : "memory");
        while (!done) {
            asm volatile(
                "{\n\t.reg .pred p;\n\t"
                "mbarrier.try_wait.parity.acquire.cta.shared::cta.b64 p, [%1], 0, 0x989680;\n\t"
                "selp.b32 %0, 1, 0, p;\n\t}"
                : "=r"(done) : "r"(mbar_a) : "memory");
        }
    }
    __syncthreads();                             // all lanes past wait + halo fill

    // ---- per-row: own chunk from smem, G-frame, chunk-max plane ----
    const float tb = (float)(4 * t);
    float g[RPB][4];
    #pragma unroll
    for (int j = 0; j < RPB; j++) {
        float4 a = ((const float4*)&raw[j][0])[t];
        g[j][0] = a.x - tb;
        g[j][1] = a.y - (tb + 1.0f);
        g[j][2] = a.z - (tb + 2.0f);
        g[j][3] = a.w - (tb + 3.0f);
        sM[j][t] = fmaxf(fmaxf(g[j][0], g[j][1]), fmaxf(g[j][2], g[j][3]));
    }
    if (t < 64) {                                // halo chunk maxes
        const int j2 = t >> 4, ht = t & 15;
        float4 a = ((const float4*)&raw[j2][0])[NCHK + ht];
        const float hb = (float)(SEGF + 4 * ht);
        const float m = fmaxf(fmaxf(a.x - hb,          a.y - (hb + 1.0f)),
                              fmaxf(a.z - (hb + 2.0f), a.w - (hb + 3.0f)));
        sM[j2][NCHK + ht] = m;
    }
    __syncthreads();

    // ---- combine + store ----
    #pragma unroll
    for (int j = 0; j < RPB; j++) {
        float mid = sM[j][t + 1];
        #pragma unroll
        for (int k = 2; k <= 15; k++)
            mid = fmaxf(mid, sM[j][t + k]);

        // B-prefix of chunk t+16 straight from raw
        float4 b = ((const float4*)&raw[j][0])[t + 16];
        const float bb = tb + 64.0f;
        const float B0 = b.x - bb;
        const float B1 = fmaxf(B0, b.y - (bb + 1.0f));
        const float B2 = fmaxf(B1, b.z - (bb + 2.0f));
        const float B3 = fmaxf(B2, b.w - (bb + 3.0f));

        const float suf2 = g[j][3];
        const float suf1 = fmaxf(g[j][2], suf2);
        const float suf0 = fmaxf(g[j][1], suf1);

        float w, r0, r1, r2, r3;
        w = fmaxf(fmaxf(suf0, mid), B0); r0 = fmaxf(w - g[j][0], 0.0f);
        w = fmaxf(fmaxf(suf1, mid), B1); r1 = fmaxf(w - g[j][1], 0.0f);
        w = fmaxf(fmaxf(suf2, mid), B2); r2 = fmaxf(w - g[j][2], 0.0f);
        w = fmaxf(mid, B3);              r3 = fmaxf(w - g[j][3], 0.0f);

        ((float4*)(out + base0 + (size_t)j * ROW))[t] = make_float4(r0, r1, r2, r3);
    }
}

extern "C" void kernel_launch(void* const* d_in, const int* in_sizes, int n_in,
                              void* d_out, int out_size)
{
    const float* hf  = (const float*)d_in[0];
    float*       out = (float*)d_out;
    (void)in_sizes; (void)n_in; (void)out_size;
    cudaFuncSetAttribute(h2i_kernel,
                         cudaFuncAttributePreferredSharedMemoryCarveout,
                         cudaSharedmemCarveoutMaxShared);
    // 256 row-groups x 4 segments = 1024 blocks; 7/SM -> single wave
    h2i_kernel<<<(NROWS / RPB) * NSEG, THREADS>>>(hf, out);
}